// round 4
// baseline (speedup 1.0000x reference)
#include <cuda_runtime.h>
#include <cuda_bf16.h>
#include <cuda_fp16.h>

// Problem constants (fixed by the dataset).
#define NMAX 50000
#define CAP  64           // max in-degree bucket (Poisson mean 25; P(>64)~e-107)
#define DH   64
#define BGR  512

// ---------------- scratch (static device memory; no allocations) -----------
__device__ int     g_cnt [NMAX];                  // in-degree (excl. self loop)
__device__ float   g_dinv[NMAX];                  // rsqrt(deg+1)
__device__ int     g_csr [(size_t)NMAX * CAP];    // bucketed incoming src lists
__device__ __half2 g_h1  [(size_t)NMAX * 32];     // layer outputs (ping, fp16)
__device__ __half2 g_h2  [(size_t)NMAX * 32];     // layer outputs (pong, fp16)
__device__ __half2 g_g   [(size_t)NMAX * 32];     // dinv-scaled GEMM output
__device__ float   g_pool[BGR * DH];              // per-graph feature sums
__device__ int     g_pcnt[BGR];                   // per-graph node counts

// ---------------- setup kernels --------------------------------------------
__global__ void zero_kernel(int n) {
    int i = blockIdx.x * blockDim.x + threadIdx.x;
    if (i < n)        g_cnt[i]  = 0;
    if (i < BGR * DH) g_pool[i] = 0.0f;
    if (i < BGR)      g_pcnt[i] = 0;
}

__global__ void csr_build_kernel(const int* __restrict__ ei, int e_count) {
    int e = blockIdx.x * blockDim.x + threadIdx.x;
    if (e >= e_count) return;
    int src = ei[e];
    int dst = ei[e_count + e];
    int slot = atomicAdd(&g_cnt[dst], 1);
    if (slot < CAP) g_csr[(size_t)dst * CAP + slot] = src;
}

__global__ void node_prep_kernel(const int* __restrict__ batch, int n) {
    int i = blockIdx.x * blockDim.x + threadIdx.x;
    if (i >= n) return;
    g_dinv[i] = rsqrtf((float)g_cnt[i] + 1.0f);   // +1 for self loop
    atomicAdd(&g_pcnt[batch[i]], 1);
}

// ---------------- GEMM via mma.sync.m16n8k16 (fp16 in, fp32 acc) -----------
// out[r][c] = dinv[r] * sum_k hin[r][k] * W[c][k], written fp16 to g_g.
// which==0: A comes from fp32 x (converted in-register). else from fp16 h1/h2.
// Fragment mapping (g = lane>>2, t = lane&3):
//   A: a0=(row g, k 2t..), a1=(g+8, 2t..), a2=(g, 2t+8..), a3=(g+8, 2t+8..)
//   B: b0=(k 2t.., n g),   b1=(k 2t+8.., n g)   [= W[n][k] row-major pairs]
__global__ __launch_bounds__(256, 1) void gemm_mma_kernel(
    const float* __restrict__ x_ext, int which, const float* __restrict__ W,
    int n)
{
    const __half2* hin = (which == 1) ? g_h1 : g_h2;

    int lane = threadIdx.x & 31;
    int g = lane >> 2, t = lane & 3;

    // Load + convert W into resident B fragments (broadcast; L1 served).
    unsigned b[4][8][2];
#pragma unroll
    for (int kc = 0; kc < 4; kc++)
#pragma unroll
        for (int nt = 0; nt < 8; nt++) {
            const float* wr = &W[(nt * 8 + g) * 64 + kc * 16 + 2 * t];
            float2 x0 = *(const float2*)(wr);
            float2 x1 = *(const float2*)(wr + 8);
            __half2 h0 = __floats2half2_rn(x0.x, x0.y);
            __half2 h1 = __floats2half2_rn(x1.x, x1.y);
            b[kc][nt][0] = *(unsigned*)&h0;
            b[kc][nt][1] = *(unsigned*)&h1;
        }

    int warp_id = (blockIdx.x * blockDim.x + threadIdx.x) >> 5;
    int nwarps  = (gridDim.x * blockDim.x) >> 5;
    int ntiles  = (n + 15) >> 4;

    for (int rt = warp_id; rt < ntiles; rt += nwarps) {
        int row0 = rt * 16;
        int r_lo = row0 + g;
        int r_hi = row0 + g + 8;
        bool ok_lo = (r_lo < n), ok_hi = (r_hi < n);

        unsigned a[4][4];
        if (which == 0) {
            const float* plo = x_ext + (size_t)r_lo * 64;
            const float* phi = x_ext + (size_t)r_hi * 64;
#pragma unroll
            for (int kc = 0; kc < 4; kc++) {
                int k0 = kc * 16 + 2 * t;
                if (ok_lo) {
                    float2 v0 = *(const float2*)&plo[k0];
                    float2 v1 = *(const float2*)&plo[k0 + 8];
                    __half2 q0 = __floats2half2_rn(v0.x, v0.y);
                    __half2 q1 = __floats2half2_rn(v1.x, v1.y);
                    a[kc][0] = *(unsigned*)&q0; a[kc][2] = *(unsigned*)&q1;
                } else { a[kc][0] = 0u; a[kc][2] = 0u; }
                if (ok_hi) {
                    float2 v0 = *(const float2*)&phi[k0];
                    float2 v1 = *(const float2*)&phi[k0 + 8];
                    __half2 q0 = __floats2half2_rn(v0.x, v0.y);
                    __half2 q1 = __floats2half2_rn(v1.x, v1.y);
                    a[kc][1] = *(unsigned*)&q0; a[kc][3] = *(unsigned*)&q1;
                } else { a[kc][1] = 0u; a[kc][3] = 0u; }
            }
        } else {
            const __half2* plo = hin + (size_t)r_lo * 32;
            const __half2* phi = hin + (size_t)r_hi * 32;
#pragma unroll
            for (int kc = 0; kc < 4; kc++) {
                if (ok_lo) {
                    a[kc][0] = *(const unsigned*)&plo[kc * 8 + t];
                    a[kc][2] = *(const unsigned*)&plo[kc * 8 + t + 4];
                } else { a[kc][0] = 0u; a[kc][2] = 0u; }
                if (ok_hi) {
                    a[kc][1] = *(const unsigned*)&phi[kc * 8 + t];
                    a[kc][3] = *(const unsigned*)&phi[kc * 8 + t + 4];
                } else { a[kc][1] = 0u; a[kc][3] = 0u; }
            }
        }

        float c[8][4];
#pragma unroll
        for (int nt = 0; nt < 8; nt++) { c[nt][0]=0.f; c[nt][1]=0.f; c[nt][2]=0.f; c[nt][3]=0.f; }

#pragma unroll
        for (int kc = 0; kc < 4; kc++)
#pragma unroll
            for (int nt = 0; nt < 8; nt++) {
                asm volatile(
                    "mma.sync.aligned.m16n8k16.row.col.f32.f16.f16.f32 "
                    "{%0,%1,%2,%3}, {%4,%5,%6,%7}, {%8,%9}, {%0,%1,%2,%3};"
                    : "+f"(c[nt][0]), "+f"(c[nt][1]), "+f"(c[nt][2]), "+f"(c[nt][3])
                    : "r"(a[kc][0]), "r"(a[kc][1]), "r"(a[kc][2]), "r"(a[kc][3]),
                      "r"(b[kc][nt][0]), "r"(b[kc][nt][1]));
            }

        if (ok_lo) {
            float dlo = g_dinv[r_lo];
            __half2* olo = g_g + (size_t)r_lo * 32;
#pragma unroll
            for (int nt = 0; nt < 8; nt++)
                olo[nt * 4 + t] = __floats2half2_rn(c[nt][0] * dlo, c[nt][1] * dlo);
        }
        if (ok_hi) {
            float dhi = g_dinv[r_hi];
            __half2* ohi = g_g + (size_t)r_hi * 32;
#pragma unroll
            for (int nt = 0; nt < 8; nt++)
                ohi[nt * 4 + t] = __floats2half2_rn(c[nt][2] * dhi, c[nt][3] * dhi);
        }
    }
}

// ---------------- aggregation: one warp per destination node ----------------
// acc = g[i] (self loop) + sum over incoming srcs of g[src]   (g is fp16)
// out = relu(dinv[i]*acc + bias); mode 1/2 -> write h1/h2 (fp16), 3 -> pool
__global__ __launch_bounds__(256) void agg_kernel(
    const float* __restrict__ bias,
    const int*   __restrict__ batch,
    int mode, int n)
{
    int w = (blockIdx.x * blockDim.x + threadIdx.x) >> 5;
    if (w >= n) return;
    int lane = threadIdx.x & 31;
    int c0 = lane * 2;

    float2 acc = __half22float2(g_g[(size_t)w * 32 + lane]);  // self loop
    float2 acc2 = make_float2(0.f, 0.f);

    int cnum = min(g_cnt[w], CAP);
    const int* lst = &g_csr[(size_t)w * CAP];

    int e = 0;
    for (; e + 8 <= cnum; e += 8) {
        int4 sa = *(const int4*)&lst[e];                      // uniform broadcast
        int4 sb = *(const int4*)&lst[e + 4];
        float2 v0 = __half22float2(g_g[(size_t)sa.x * 32 + lane]);
        float2 v1 = __half22float2(g_g[(size_t)sa.y * 32 + lane]);
        float2 v2 = __half22float2(g_g[(size_t)sa.z * 32 + lane]);
        float2 v3 = __half22float2(g_g[(size_t)sa.w * 32 + lane]);
        float2 v4 = __half22float2(g_g[(size_t)sb.x * 32 + lane]);
        float2 v5 = __half22float2(g_g[(size_t)sb.y * 32 + lane]);
        float2 v6 = __half22float2(g_g[(size_t)sb.z * 32 + lane]);
        float2 v7 = __half22float2(g_g[(size_t)sb.w * 32 + lane]);
        acc.x  += (v0.x + v1.x) + (v2.x + v3.x);
        acc.y  += (v0.y + v1.y) + (v2.y + v3.y);
        acc2.x += (v4.x + v5.x) + (v6.x + v7.x);
        acc2.y += (v4.y + v5.y) + (v6.y + v7.y);
    }
    for (; e + 4 <= cnum; e += 4) {
        int4 s4 = *(const int4*)&lst[e];
        float2 v0 = __half22float2(g_g[(size_t)s4.x * 32 + lane]);
        float2 v1 = __half22float2(g_g[(size_t)s4.y * 32 + lane]);
        float2 v2 = __half22float2(g_g[(size_t)s4.z * 32 + lane]);
        float2 v3 = __half22float2(g_g[(size_t)s4.w * 32 + lane]);
        acc.x += (v0.x + v1.x) + (v2.x + v3.x);
        acc.y += (v0.y + v1.y) + (v2.y + v3.y);
    }
    for (; e < cnum; e++) {
        int s = lst[e];
        float2 v = __half22float2(g_g[(size_t)s * 32 + lane]);
        acc.x += v.x;
        acc.y += v.y;
    }
    acc.x += acc2.x;
    acc.y += acc2.y;

    float dv = g_dinv[w];
    float ox = fmaxf(fmaf(dv, acc.x, bias[c0    ]), 0.0f);
    float oy = fmaxf(fmaf(dv, acc.y, bias[c0 + 1]), 0.0f);

    if (mode == 1) {
        g_h1[(size_t)w * 32 + lane] = __floats2half2_rn(ox, oy);
    } else if (mode == 2) {
        g_h2[(size_t)w * 32 + lane] = __floats2half2_rn(ox, oy);
    } else {
        int b = batch[w];
        atomicAdd(&g_pool[b * 64 + c0    ], ox);
        atomicAdd(&g_pool[b * 64 + c0 + 1], oy);
    }
}

// ---------------- final: out[b][o] = mean-pool(b) . Wl[o] + bl[o] -----------
__global__ void final_kernel(const float* __restrict__ Wl,
                             const float* __restrict__ bl,
                             float* __restrict__ out)
{
    int t = blockIdx.x * blockDim.x + threadIdx.x;
    if (t >= BGR * 16) return;
    int b = t >> 4, o = t & 15;
    float inv = 1.0f / fmaxf((float)g_pcnt[b], 1.0f);
    const float* pr = &g_pool[b * 64];
    const float* wr = &Wl[o * 64];
    float s = 0.0f;
#pragma unroll
    for (int k = 0; k < 64; k++) s = fmaf(pr[k], wr[k], s);
    out[t] = fmaf(s, inv, bl[o]);
}

// ---------------- launch ----------------------------------------------------
extern "C" void kernel_launch(void* const* d_in, const int* in_sizes, int n_in,
                              void* d_out, int out_size)
{
    const float* x     = (const float*)d_in[0];
    const int*   ei    = (const int*)  d_in[1];
    const int*   batch = (const int*)  d_in[2];
    const float* W1    = (const float*)d_in[3];
    const float* b1    = (const float*)d_in[4];
    const float* W2    = (const float*)d_in[5];
    const float* b2    = (const float*)d_in[6];
    const float* W3    = (const float*)d_in[7];
    const float* b3    = (const float*)d_in[8];
    const float* Wl    = (const float*)d_in[9];
    const float* bl    = (const float*)d_in[10];
    float* out = (float*)d_out;

    int n = in_sizes[0] / 64;   // 50000
    int e = in_sizes[1] / 2;    // 1250000

    int nb_n = (n + 255) / 256;
    int nb_e = (e + 255) / 256;
    int nb_a = (n * 32 + 255) / 256;       // agg: 1 warp / node
    int ntiles = (n + 15) / 16;
    int nb_m = (ntiles + 7) / 8;           // gemm: 1 tile / warp

    zero_kernel<<<nb_n, 256>>>(n);
    csr_build_kernel<<<nb_e, 256>>>(ei, e);
    node_prep_kernel<<<nb_n, 256>>>(batch, n);

    gemm_mma_kernel<<<nb_m, 256>>>(x, 0, W1, n);
    agg_kernel<<<nb_a, 256>>>(b1, batch, 1, n);

    gemm_mma_kernel<<<nb_m, 256>>>(x, 1, W2, n);
    agg_kernel<<<nb_a, 256>>>(b2, batch, 2, n);

    gemm_mma_kernel<<<nb_m, 256>>>(x, 2, W3, n);
    agg_kernel<<<nb_a, 256>>>(b3, batch, 3, n);

    final_kernel<<<(BGR * 16 + 255) / 256, 256>>>(Wl, bl, out);
}

// round 5
// speedup vs baseline: 1.1165x; 1.1165x over previous
#include <cuda_runtime.h>
#include <cuda_bf16.h>
#include <cuda_fp16.h>

// Problem constants (fixed by the dataset).
#define NMAX 50000
#define CAP  64           // max in-degree bucket (Poisson mean 25; P(>64)~e-107)
#define DH   64
#define BGR  512

// ---------------- scratch (static device memory; no allocations) -----------
__device__ int     g_cnt [NMAX];                  // in-degree (excl. self loop)
__device__ float   g_dinv[NMAX];                  // rsqrt(deg+1)
__device__ int     g_csr [(size_t)NMAX * CAP];    // bucketed incoming src lists
__device__ __half2 g_h1  [(size_t)NMAX * 32];     // layer outputs (ping, fp16)
__device__ __half2 g_h2  [(size_t)NMAX * 32];     // layer outputs (pong, fp16)
__device__ __half2 g_g   [(size_t)NMAX * 32];     // dinv-scaled GEMM output
__device__ float   g_pool[BGR * DH];              // per-graph feature sums
__device__ int     g_pcnt[BGR];                   // per-graph node counts

// ---------------- setup kernels --------------------------------------------
__global__ void zero_kernel(int n) {
    int i = blockIdx.x * blockDim.x + threadIdx.x;
    if (i < n)        g_cnt[i]  = 0;
    if (i < BGR * DH) g_pool[i] = 0.0f;
    if (i < BGR)      g_pcnt[i] = 0;
}

__global__ void csr_build_kernel(const int* __restrict__ ei, int e_count) {
    int e = blockIdx.x * blockDim.x + threadIdx.x;
    if (e >= e_count) return;
    int src = ei[e];
    int dst = ei[e_count + e];
    int slot = atomicAdd(&g_cnt[dst], 1);
    if (slot < CAP) g_csr[(size_t)dst * CAP + slot] = src;
}

__global__ void node_prep_kernel(const int* __restrict__ batch, int n) {
    int i = blockIdx.x * blockDim.x + threadIdx.x;
    if (i >= n) return;
    g_dinv[i] = rsqrtf((float)g_cnt[i] + 1.0f);   // +1 for self loop
    atomicAdd(&g_pcnt[batch[i]], 1);
}

// ---------------- GEMM via mma.sync.m16n8k16 (fp16 in, fp32 acc) -----------
// out[r][c] = dinv[r] * sum_k hin[r][k] * W[c][k], written fp16 to g_g.
// which==0: A comes from fp32 x (converted in-register), else fp16 h1/h2.
// B fragments live in SMEM (not registers) to keep occupancy high.
// Fragment mapping (g = lane>>2, t = lane&3):
//   A: a0=(row g, k 2t..), a1=(g+8, 2t..), a2=(g, 2t+8..), a3=(g+8, 2t+8..)
//   B: b0=(k 2t.., n g),   b1=(k 2t+8.., n g)   [= W[n][k] row-major pairs]
// SMEM layout: bs[(((kc*8+nt)*8+g)*4+t)*2 + j] -> per-(kc,nt) lane loads are
// an 8-byte LDS.64 at distinct addresses (conflict-free).
__global__ __launch_bounds__(256) void gemm_mma_kernel(
    const float* __restrict__ x_ext, int which, const float* __restrict__ W,
    int n)
{
    const __half2* hin = (which == 1) ? g_h1 : g_h2;

    __shared__ unsigned bs[2048];      // 8 KB of B fragments

    int tid = threadIdx.x;
#pragma unroll
    for (int i = 0; i < 8; i++) {
        int flat = tid + i * 256;          // [0,2048)
        int kc =  flat >> 9;
        int nt = (flat >> 6) & 7;
        int gg = (flat >> 3) & 7;
        int tt = (flat >> 1) & 3;
        int j  =  flat & 1;
        int col = nt * 8 + gg;
        int k   = kc * 16 + 2 * tt + 8 * j;
        __half2 h = __floats2half2_rn(W[col * 64 + k], W[col * 64 + k + 1]);
        bs[flat] = *(unsigned*)&h;
    }
    __syncthreads();

    int lane = tid & 31;
    int g = lane >> 2, t = lane & 3;

    int warp_id = (blockIdx.x * blockDim.x + tid) >> 5;
    int nwarps  = (gridDim.x * blockDim.x) >> 5;
    int ntiles  = (n + 15) >> 4;

    for (int rt = warp_id; rt < ntiles; rt += nwarps) {
        int row0 = rt * 16;
        int r_lo = row0 + g;
        int r_hi = row0 + g + 8;
        bool ok_lo = (r_lo < n), ok_hi = (r_hi < n);

        unsigned a[4][4];
        if (which == 0) {
            const float* plo = x_ext + (size_t)r_lo * 64;
            const float* phi = x_ext + (size_t)r_hi * 64;
#pragma unroll
            for (int kc = 0; kc < 4; kc++) {
                int k0 = kc * 16 + 2 * t;
                if (ok_lo) {
                    float2 v0 = *(const float2*)&plo[k0];
                    float2 v1 = *(const float2*)&plo[k0 + 8];
                    __half2 q0 = __floats2half2_rn(v0.x, v0.y);
                    __half2 q1 = __floats2half2_rn(v1.x, v1.y);
                    a[kc][0] = *(unsigned*)&q0; a[kc][2] = *(unsigned*)&q1;
                } else { a[kc][0] = 0u; a[kc][2] = 0u; }
                if (ok_hi) {
                    float2 v0 = *(const float2*)&phi[k0];
                    float2 v1 = *(const float2*)&phi[k0 + 8];
                    __half2 q0 = __floats2half2_rn(v0.x, v0.y);
                    __half2 q1 = __floats2half2_rn(v1.x, v1.y);
                    a[kc][1] = *(unsigned*)&q0; a[kc][3] = *(unsigned*)&q1;
                } else { a[kc][1] = 0u; a[kc][3] = 0u; }
            }
        } else {
            const __half2* plo = hin + (size_t)r_lo * 32;
            const __half2* phi = hin + (size_t)r_hi * 32;
#pragma unroll
            for (int kc = 0; kc < 4; kc++) {
                if (ok_lo) {
                    a[kc][0] = *(const unsigned*)&plo[kc * 8 + t];
                    a[kc][2] = *(const unsigned*)&plo[kc * 8 + t + 4];
                } else { a[kc][0] = 0u; a[kc][2] = 0u; }
                if (ok_hi) {
                    a[kc][1] = *(const unsigned*)&phi[kc * 8 + t];
                    a[kc][3] = *(const unsigned*)&phi[kc * 8 + t + 4];
                } else { a[kc][1] = 0u; a[kc][3] = 0u; }
            }
        }

        float c[8][4];
#pragma unroll
        for (int nt = 0; nt < 8; nt++) { c[nt][0]=0.f; c[nt][1]=0.f; c[nt][2]=0.f; c[nt][3]=0.f; }

#pragma unroll
        for (int kc = 0; kc < 4; kc++)
#pragma unroll
            for (int nt = 0; nt < 8; nt++) {
                uint2 bb = *(const uint2*)&bs[(((kc * 8 + nt) * 8 + g) * 4 + t) * 2];
                asm volatile(
                    "mma.sync.aligned.m16n8k16.row.col.f32.f16.f16.f32 "
                    "{%0,%1,%2,%3}, {%4,%5,%6,%7}, {%8,%9}, {%0,%1,%2,%3};"
                    : "+f"(c[nt][0]), "+f"(c[nt][1]), "+f"(c[nt][2]), "+f"(c[nt][3])
                    : "r"(a[kc][0]), "r"(a[kc][1]), "r"(a[kc][2]), "r"(a[kc][3]),
                      "r"(bb.x), "r"(bb.y));
            }

        if (ok_lo) {
            float dlo = g_dinv[r_lo];
            __half2* olo = g_g + (size_t)r_lo * 32;
#pragma unroll
            for (int nt = 0; nt < 8; nt++)
                olo[nt * 4 + t] = __floats2half2_rn(c[nt][0] * dlo, c[nt][1] * dlo);
        }
        if (ok_hi) {
            float dhi = g_dinv[r_hi];
            __half2* ohi = g_g + (size_t)r_hi * 32;
#pragma unroll
            for (int nt = 0; nt < 8; nt++)
                ohi[nt * 4 + t] = __floats2half2_rn(c[nt][2] * dhi, c[nt][3] * dhi);
        }
    }
}

// ---------------- aggregation: one warp per destination node ----------------
// acc = g[i] (self loop) + sum over incoming srcs of g[src]   (g is fp16)
// out = relu(dinv[i]*acc + bias); mode 1/2 -> write h1/h2 (fp16), 3 -> pool
__global__ __launch_bounds__(512) void agg_kernel(
    const float* __restrict__ bias,
    const int*   __restrict__ batch,
    int mode, int n)
{
    int w = (blockIdx.x * blockDim.x + threadIdx.x) >> 5;
    if (w >= n) return;
    int lane = threadIdx.x & 31;
    int c0 = lane * 2;

    float2 acc = __half22float2(g_g[(size_t)w * 32 + lane]);  // self loop
    float2 acc2 = make_float2(0.f, 0.f);

    int cnum = min(g_cnt[w], CAP);
    const int* lst = &g_csr[(size_t)w * CAP];

    int e = 0;
    for (; e + 8 <= cnum; e += 8) {
        int4 sa = *(const int4*)&lst[e];                      // uniform broadcast
        int4 sb = *(const int4*)&lst[e + 4];
        float2 v0 = __half22float2(g_g[(size_t)sa.x * 32 + lane]);
        float2 v1 = __half22float2(g_g[(size_t)sa.y * 32 + lane]);
        float2 v2 = __half22float2(g_g[(size_t)sa.z * 32 + lane]);
        float2 v3 = __half22float2(g_g[(size_t)sa.w * 32 + lane]);
        float2 v4 = __half22float2(g_g[(size_t)sb.x * 32 + lane]);
        float2 v5 = __half22float2(g_g[(size_t)sb.y * 32 + lane]);
        float2 v6 = __half22float2(g_g[(size_t)sb.z * 32 + lane]);
        float2 v7 = __half22float2(g_g[(size_t)sb.w * 32 + lane]);
        acc.x  += (v0.x + v1.x) + (v2.x + v3.x);
        acc.y  += (v0.y + v1.y) + (v2.y + v3.y);
        acc2.x += (v4.x + v5.x) + (v6.x + v7.x);
        acc2.y += (v4.y + v5.y) + (v6.y + v7.y);
    }
    for (; e + 4 <= cnum; e += 4) {
        int4 s4 = *(const int4*)&lst[e];
        float2 v0 = __half22float2(g_g[(size_t)s4.x * 32 + lane]);
        float2 v1 = __half22float2(g_g[(size_t)s4.y * 32 + lane]);
        float2 v2 = __half22float2(g_g[(size_t)s4.z * 32 + lane]);
        float2 v3 = __half22float2(g_g[(size_t)s4.w * 32 + lane]);
        acc.x += (v0.x + v1.x) + (v2.x + v3.x);
        acc.y += (v0.y + v1.y) + (v2.y + v3.y);
    }
    for (; e < cnum; e++) {
        int s = lst[e];
        float2 v = __half22float2(g_g[(size_t)s * 32 + lane]);
        acc.x += v.x;
        acc.y += v.y;
    }
    acc.x += acc2.x;
    acc.y += acc2.y;

    float dv = g_dinv[w];
    float ox = fmaxf(fmaf(dv, acc.x, bias[c0    ]), 0.0f);
    float oy = fmaxf(fmaf(dv, acc.y, bias[c0 + 1]), 0.0f);

    if (mode == 1) {
        g_h1[(size_t)w * 32 + lane] = __floats2half2_rn(ox, oy);
    } else if (mode == 2) {
        g_h2[(size_t)w * 32 + lane] = __floats2half2_rn(ox, oy);
    } else {
        int b = batch[w];
        atomicAdd(&g_pool[b * 64 + c0    ], ox);
        atomicAdd(&g_pool[b * 64 + c0 + 1], oy);
    }
}

// ---------------- final: out[b][o] = mean-pool(b) . Wl[o] + bl[o] -----------
__global__ void final_kernel(const float* __restrict__ Wl,
                             const float* __restrict__ bl,
                             float* __restrict__ out)
{
    int t = blockIdx.x * blockDim.x + threadIdx.x;
    if (t >= BGR * 16) return;
    int b = t >> 4, o = t & 15;
    float inv = 1.0f / fmaxf((float)g_pcnt[b], 1.0f);
    const float* pr = &g_pool[b * 64];
    const float* wr = &Wl[o * 64];
    float s = 0.0f;
#pragma unroll
    for (int k = 0; k < 64; k++) s = fmaf(pr[k], wr[k], s);
    out[t] = fmaf(s, inv, bl[o]);
}

// ---------------- launch ----------------------------------------------------
extern "C" void kernel_launch(void* const* d_in, const int* in_sizes, int n_in,
                              void* d_out, int out_size)
{
    const float* x     = (const float*)d_in[0];
    const int*   ei    = (const int*)  d_in[1];
    const int*   batch = (const int*)  d_in[2];
    const float* W1    = (const float*)d_in[3];
    const float* b1    = (const float*)d_in[4];
    const float* W2    = (const float*)d_in[5];
    const float* b2    = (const float*)d_in[6];
    const float* W3    = (const float*)d_in[7];
    const float* b3    = (const float*)d_in[8];
    const float* Wl    = (const float*)d_in[9];
    const float* bl    = (const float*)d_in[10];
    float* out = (float*)d_out;

    int n = in_sizes[0] / 64;   // 50000
    int e = in_sizes[1] / 2;    // 1250000

    int nb_n = (n + 255) / 256;
    int nb_e = (e + 255) / 256;
    int nb_a = (n * 32 + 511) / 512;       // agg: 1 warp / node, 16 warps/block
    int ntiles = (n + 15) / 16;
    int nb_m = (ntiles + 7) / 8;           // gemm: 1 tile / warp

    zero_kernel<<<nb_n, 256>>>(n);
    csr_build_kernel<<<nb_e, 256>>>(ei, e);
    node_prep_kernel<<<nb_n, 256>>>(batch, n);

    gemm_mma_kernel<<<nb_m, 256>>>(x, 0, W1, n);
    agg_kernel<<<nb_a, 512>>>(b1, batch, 1, n);

    gemm_mma_kernel<<<nb_m, 256>>>(x, 1, W2, n);
    agg_kernel<<<nb_a, 512>>>(b2, batch, 2, n);

    gemm_mma_kernel<<<nb_m, 256>>>(x, 2, W3, n);
    agg_kernel<<<nb_a, 512>>>(b3, batch, 3, n);

    final_kernel<<<(BGR * 16 + 255) / 256, 256>>>(Wl, bl, out);
}